// round 2
// baseline (speedup 1.0000x reference)
#include <cuda_runtime.h>
#include <cuda_bf16.h>
#include <cstdio>

// Problem constants
#define BB 8
#define IC 1024
#define OC 512
#define HH 64
#define WW 48
#define HW 3072            // H*W
#define AA 9
#define SZ_PROB (8*18*3072)   // 442368
#define SZ_BBOX (8*36*3072)   // 884736
#define OUT_LCLS (SZ_PROB + SZ_BBOX)     // 1327104
#define OUT_LBOX (SZ_PROB + SZ_BBOX + 1) // 1327105

// -------- device-global scratch (no allocations allowed) --------
__device__ float g_conv1[(size_t)BB*OC*HW];   // 12.58M floats
__device__ float g_wt[(size_t)IC*9*OC];       // transposed conv weights [ic*9+k][oc]
__device__ float g_wh[512*56];                // transposed head weights [ic][56] (18 cls + 36 bbox + 2 pad)
__device__ float g_cls[SZ_PROB];              // raw cls scores
__device__ float g_acc[3];                    // nll_sum, valid_cnt, box_sum

// -------- f32x2 helpers (sm_103a packed fp32) --------
__device__ __forceinline__ unsigned long long pk1(float x) {
  unsigned long long r; unsigned int u = __float_as_uint(x);
  asm("mov.b64 %0, {%1, %1};" : "=l"(r) : "r"(u));
  return r;
}
__device__ __forceinline__ unsigned long long pk2(float lo, float hi) {
  unsigned long long r;
  asm("mov.b64 %0, {%1, %2};" : "=l"(r) : "r"(__float_as_uint(lo)), "r"(__float_as_uint(hi)));
  return r;
}
__device__ __forceinline__ void upk(unsigned long long v, float& lo, float& hi) {
  unsigned int a, b;
  asm("mov.b64 {%0, %1}, %2;" : "=r"(a), "=r"(b) : "l"(v));
  lo = __uint_as_float(a); hi = __uint_as_float(b);
}
__device__ __forceinline__ void fma2(unsigned long long& acc, unsigned long long a, unsigned long long b) {
  asm("fma.rn.f32x2 %0, %1, %2, %0;" : "+l"(acc) : "l"(a), "l"(b));
}

// -------- block reduce --------
__device__ __forceinline__ float blockReduceSum(float v) {
  __shared__ float sh[32];
  __syncthreads();
  #pragma unroll
  for (int o = 16; o; o >>= 1) v += __shfl_down_sync(0xffffffffu, v, o);
  int lane = threadIdx.x & 31, wid = threadIdx.x >> 5;
  if (lane == 0) sh[wid] = v;
  __syncthreads();
  int nw = blockDim.x >> 5;
  v = (threadIdx.x < (unsigned)nw) ? sh[threadIdx.x] : 0.f;
  if (wid == 0) {
    #pragma unroll
    for (int o = 16; o; o >>= 1) v += __shfl_down_sync(0xffffffffu, v, o);
  }
  return v;
}

// -------- K0: zero accumulators --------
__global__ void k_zero() {
  if (threadIdx.x < 3) g_acc[threadIdx.x] = 0.f;
}

// -------- K: transpose conv weights  W[oc][ic][3][3] -> g_wt[(ic*9+k)][oc] --------
__global__ void k_transpose_w(const float* __restrict__ Wc) {
  int i = blockIdx.x * 256 + threadIdx.x;          // 9216*512 total
  if (i >= 9216 * 512) return;
  int oc = i & 511;
  int row = i >> 9;                                // ic*9 + k
  g_wt[i] = Wc[(size_t)oc * 9216 + row];
}

// -------- K: transpose head weights -> g_wh[ic][56] --------
__global__ void k_transpose_h(const float* __restrict__ Wcls, const float* __restrict__ Wbb) {
  int i = blockIdx.x * 256 + threadIdx.x;          // 512*56
  if (i >= 512 * 56) return;
  int ic = i / 56, ch = i - ic * 56;
  float v = 0.f;
  if (ch < 18) v = Wcls[ch * 512 + ic];
  else if (ch < 54) v = Wbb[(ch - 18) * 512 + ic];
  g_wh[i] = v;
}

// -------- K1: 3x3 conv + bias + relu  (implicit GEMM, f32x2 over oc-pairs) --------
// block: 128 oc x (2 rows x 48 w), 256 threads, ic-chunks of 8
__global__ void __launch_bounds__(256, 2) k_conv(const float* __restrict__ x,
                                                 const float* __restrict__ bconv) {
  __shared__ __align__(16) float sW[72 * 128];   // [ic(8)*9+k][128 oc]
  __shared__ float sX[8 * 4 * 50];               // [ic][4 rows][50 cols (w=-1..48)]

  const int b   = blockIdx.z;
  const int h0  = blockIdx.y * 2;
  const int oc0 = blockIdx.x * 128;
  const int tid = threadIdx.x;
  const int wg  = tid & 15;        // 16 w-groups
  const int og  = tid >> 4;        // 16 oc-groups of 8
  const int w0  = wg * 3;
  const int ocT = og * 8;

  unsigned long long acc[4][2][3];
  #pragma unroll
  for (int j = 0; j < 4; j++) {
    unsigned long long bp = pk2(bconv[oc0 + ocT + 2*j], bconv[oc0 + ocT + 2*j + 1]);
    #pragma unroll
    for (int r = 0; r < 2; r++)
      #pragma unroll
      for (int c = 0; c < 3; c++)
        acc[j][r][c] = bp;
  }

  const float* xb = x + (size_t)b * IC * HW;

  #pragma unroll 1
  for (int ic0 = 0; ic0 < IC; ic0 += 8) {
    __syncthreads();
    // stage weights: 72 rows x 128 oc (fully coalesced float4 copy)
    {
      const float4* src = (const float4*)(g_wt + (size_t)ic0 * 9 * 512 + oc0);
      float4* dst = (float4*)sW;
      #pragma unroll
      for (int i = tid; i < 72 * 32; i += 256) {
        int r = i >> 5, c = i & 31;
        dst[i] = src[r * 128 + c];
      }
    }
    // stage inputs: 8 ic x 4 rows x 50 cols (zero-padded borders)
    #pragma unroll 1
    for (int i = tid; i < 8 * 200; i += 256) {
      int ic  = i / 200;
      int rem = i - ic * 200;
      int r   = rem / 50;
      int col = rem - r * 50;
      int gh = h0 - 1 + r;
      int gw = col - 1;
      float v = 0.f;
      if ((unsigned)gh < 64u && (unsigned)gw < 48u)
        v = xb[(size_t)(ic0 + ic) * HW + gh * 48 + gw];
      sX[i] = v;
    }
    __syncthreads();

    #pragma unroll 1
    for (int ic = 0; ic < 8; ic++) {
      #pragma unroll
      for (int kh = 0; kh < 3; kh++) {
        unsigned long long px[2][5];
        #pragma unroll
        for (int r = 0; r < 2; r++)
          #pragma unroll
          for (int c = 0; c < 5; c++)
            px[r][c] = pk1(sX[(ic * 4 + kh + r) * 50 + w0 + c]);
        #pragma unroll
        for (int kw = 0; kw < 3; kw++) {
          const unsigned long long* wp =
              (const unsigned long long*)(sW + ((ic * 9 + kh * 3 + kw) << 7) + ocT);
          unsigned long long wq0 = wp[0], wq1 = wp[1], wq2 = wp[2], wq3 = wp[3];
          #pragma unroll
          for (int r = 0; r < 2; r++) {
            #pragma unroll
            for (int c = 0; c < 3; c++) {
              unsigned long long xv = px[r][c + kw];
              fma2(acc[0][r][c], wq0, xv);
              fma2(acc[1][r][c], wq1, xv);
              fma2(acc[2][r][c], wq2, xv);
              fma2(acc[3][r][c], wq3, xv);
            }
          }
        }
      }
    }
  }

  // epilogue: relu + store
  float* outp = g_conv1 + ((size_t)b * OC + oc0 + ocT) * HW + h0 * 48 + w0;
  #pragma unroll
  for (int j = 0; j < 4; j++) {
    #pragma unroll
    for (int r = 0; r < 2; r++) {
      #pragma unroll
      for (int c = 0; c < 3; c++) {
        float lo, hi; upk(acc[j][r][c], lo, hi);
        size_t base = (size_t)(2 * j) * HW + r * 48 + c;
        outp[base]       = fmaxf(lo, 0.f);
        outp[base + HW]  = fmaxf(hi, 0.f);
      }
    }
  }
}

// -------- K2: 1x1 heads (cls 18 + bbox 36 fused as 54-ch GEMM) --------
// block: 128 spatial x 54 ch, 256 threads (2 halves of 28 ch), ic-chunks of 64
__global__ void __launch_bounds__(256) k_heads(const float* __restrict__ bcls,
                                               const float* __restrict__ bbb,
                                               float* __restrict__ out) {
  __shared__ __align__(16) float sx[64 * 128];
  __shared__ __align__(16) float sw[64 * 56];
  const int t   = blockIdx.x;          // 0..191
  const int b   = t / 24;
  const int sp0 = (t % 24) * 128;
  const int tid = threadIdx.x;
  const int sp   = tid & 127;
  const int half = tid >> 7;

  float accv[28];
  #pragma unroll
  for (int j = 0; j < 28; j++) accv[j] = 0.f;

  #pragma unroll 1
  for (int ic0 = 0; ic0 < 512; ic0 += 64) {
    __syncthreads();
    {
      float4* dst = (float4*)sx;
      #pragma unroll 1
      for (int i = tid; i < 2048; i += 256) {
        int ic = i >> 5, c = i & 31;
        dst[i] = *(const float4*)(g_conv1 + (size_t)(b * 512 + ic0 + ic) * HW + sp0 + c * 4);
      }
      float4* dw = (float4*)sw;
      const float4* srw = (const float4*)(g_wh + ic0 * 56);
      #pragma unroll 1
      for (int i = tid; i < 896; i += 256) dw[i] = srw[i];
    }
    __syncthreads();
    #pragma unroll 1
    for (int ic = 0; ic < 64; ic++) {
      float xv = sx[ic * 128 + sp];
      const float* wr = sw + ic * 56 + half * 28;
      #pragma unroll
      for (int j = 0; j < 28; j++) accv[j] = fmaf(xv, wr[j], accv[j]);
    }
  }

  const int chb = half * 28;
  #pragma unroll
  for (int j = 0; j < 28; j++) {
    int ch = chb + j;
    if (ch < 54) {
      float bias = (ch < 18) ? bcls[ch] : bbb[ch - 18];
      float v = accv[j] + bias;
      if (ch < 18) g_cls[(size_t)(b * 18 + ch) * HW + sp0 + sp] = v;
      else         out[SZ_PROB + (size_t)(b * 36 + (ch - 18)) * HW + sp0 + sp] = v;
    }
  }
}

// -------- K3: paired softmax -> prob, + NLL cls loss --------
__global__ void __launch_bounds__(256) k_cls(const int* __restrict__ label,
                                             float* __restrict__ out) {
  int idx = blockIdx.x * 256 + threadIdx.x;   // < 8*9*3072 = 221184
  float nll = 0.f, cnt = 0.f;
  if (idx < BB * AA * HW) {
    int b   = idx / (AA * HW);
    int rem = idx - b * (AA * HW);
    int a   = rem / HW;
    int s   = rem - a * HW;
    float l0 = g_cls[(size_t)(b * 18 + a) * HW + s];
    float l1 = g_cls[(size_t)(b * 18 + a + 9) * HW + s];
    float m  = fmaxf(l0, l1);
    float e0 = expf(l0 - m), e1 = expf(l1 - m);
    float sum = e0 + e1;
    float inv = 1.f / sum;
    out[(size_t)(b * 18 + a) * HW + s]     = e0 * inv;
    out[(size_t)(b * 18 + a + 9) * HW + s] = e1 * inv;
    int lb = label[idx];
    if (lb >= 0) {
      float chosen = lb ? l1 : l0;
      nll = -(chosen - m - logf(sum));
      cnt = 1.f;
    }
  }
  float s1 = blockReduceSum(nll);
  if (threadIdx.x == 0) atomicAdd(&g_acc[0], s1);
  float s2 = blockReduceSum(cnt);
  if (threadIdx.x == 0) atomicAdd(&g_acc[1], s2);
}

// -------- K4: smooth-L1 box loss --------
__global__ void __launch_bounds__(256) k_box(const float* __restrict__ tgt,
                                             const float* __restrict__ iw,
                                             const float* __restrict__ ow,
                                             const float* __restrict__ bbox) {
  int i = blockIdx.x * 256 + threadIdx.x;     // < 884736
  float v = 0.f;
  if (i < SZ_BBOX) {
    float d  = iw[i] * (bbox[i] - tgt[i]);
    float ad = fabsf(d);
    float l  = (ad < (1.f / 9.f)) ? d * d * 4.5f : (ad - (1.f / 18.f));
    v = ow[i] * l;
  }
  float s = blockReduceSum(v);
  if (threadIdx.x == 0) atomicAdd(&g_acc[2], s);
}

// -------- K5: finalize scalars --------
__global__ void k_fin(float* out) {
  out[OUT_LCLS] = g_acc[0] / fmaxf(g_acc[1], 1.f);
  out[OUT_LBOX] = g_acc[2] * 0.125f;
}

extern "C" void kernel_launch(void* const* d_in, const int* in_sizes, int n_in,
                              void* d_out, int out_size) {
  const float* base_feat = (const float*)d_in[0];
  const float* W_conv    = (const float*)d_in[1];
  const float* b_conv    = (const float*)d_in[2];
  const float* W_cls     = (const float*)d_in[3];
  const float* b_cls     = (const float*)d_in[4];
  const float* W_bbox    = (const float*)d_in[5];
  const float* b_bbox    = (const float*)d_in[6];
  const int*   rpn_label = (const int*)d_in[7];
  const float* tgt       = (const float*)d_in[8];
  const float* iw        = (const float*)d_in[9];
  const float* ow        = (const float*)d_in[10];
  float* out = (float*)d_out;

  k_zero<<<1, 32>>>();
  k_transpose_w<<<(9216 * 512 + 255) / 256, 256>>>(W_conv);
  k_transpose_h<<<(512 * 56 + 255) / 256, 256>>>(W_cls, W_bbox);
  k_conv<<<dim3(4, 32, 8), 256>>>(base_feat, b_conv);
  k_heads<<<192, 256>>>(b_cls, b_bbox, out);
  k_cls<<<(BB * AA * HW + 255) / 256, 256>>>(rpn_label, out);
  k_box<<<(SZ_BBOX + 255) / 256, 256>>>(tgt, iw, ow, out + SZ_PROB);
  k_fin<<<1, 1>>>(out);
}

// round 4
// speedup vs baseline: 2.1471x; 2.1471x over previous
#include <cuda_runtime.h>
#include <cuda_bf16.h>
#include <cstdint>

#define BB 8
#define HW 3072
#define KK 9216
#define SZ_PROB (8*18*3072)
#define SZ_BBOX (8*36*3072)
#define OUT_LCLS (SZ_PROB+SZ_BBOX)
#define OUT_LBOX (SZ_PROB+SZ_BBOX+1)
#define NCH 288
#define STGB 32768
#define SMEM_HMMA (4*STGB)

// ---------------- device scratch ----------------
__device__ float g_conv1[(size_t)BB*512*HW];
__device__ __align__(256) __nv_bfloat16 g_xhi[(size_t)BB*HW*1024];
__device__ __align__(256) __nv_bfloat16 g_xlo[(size_t)BB*HW*1024];
__device__ __align__(256) __nv_bfloat16 g_whi[(size_t)512*KK];
__device__ __align__(256) __nv_bfloat16 g_wlo[(size_t)512*KK];
__device__ float g_wh[512*56];
__device__ float g_cls[SZ_PROB];
__device__ float g_acc[3];

// ---------------- PTX helpers (baseline sm_90-class only) ----------------
__device__ __forceinline__ uint32_t smem_u32(const void* p) {
  uint32_t a;
  asm("{ .reg .u64 t; cvta.to.shared.u64 t, %1; cvt.u32.u64 %0, t; }" : "=r"(a) : "l"(p));
  return a;
}
__device__ __forceinline__ void cpa16(uint32_t dst, const void* src, int sz) {
  asm volatile("cp.async.cg.shared.global [%0], [%1], 16, %2;"
               :: "r"(dst), "l"(src), "r"(sz) : "memory");
}
#define CPA_COMMIT asm volatile("cp.async.commit_group;" ::: "memory")
#define CPA_WAIT3  asm volatile("cp.async.wait_group 3;" ::: "memory")
__device__ __forceinline__ void ldsm4(uint32_t* r, uint32_t a) {
  asm volatile("ldmatrix.sync.aligned.m8n8.x4.shared.b16 {%0,%1,%2,%3}, [%4];"
    : "=r"(r[0]), "=r"(r[1]), "=r"(r[2]), "=r"(r[3]) : "r"(a));
}
__device__ __forceinline__ void ldsm2(uint32_t* r, uint32_t a) {
  asm volatile("ldmatrix.sync.aligned.m8n8.x2.shared.b16 {%0,%1}, [%2];"
    : "=r"(r[0]), "=r"(r[1]) : "r"(a));
}
__device__ __forceinline__ void mma16816(float* c, const uint32_t* a, const uint32_t* b) {
  asm volatile("mma.sync.aligned.m16n8k16.row.col.f32.bf16.bf16.f32 "
    "{%0,%1,%2,%3}, {%4,%5,%6,%7}, {%8,%9}, {%0,%1,%2,%3};"
    : "+f"(c[0]), "+f"(c[1]), "+f"(c[2]), "+f"(c[3])
    : "r"(a[0]), "r"(a[1]), "r"(a[2]), "r"(a[3]), "r"(b[0]), "r"(b[1]));
}

// ---------------- misc kernels ----------------
__device__ __forceinline__ float blockReduceSum(float v) {
  __shared__ float sh[32];
  __syncthreads();
  #pragma unroll
  for (int o = 16; o; o >>= 1) v += __shfl_down_sync(0xffffffffu, v, o);
  int lane = threadIdx.x & 31, wid = threadIdx.x >> 5;
  if (lane == 0) sh[wid] = v;
  __syncthreads();
  int nw = blockDim.x >> 5;
  v = (threadIdx.x < (unsigned)nw) ? sh[threadIdx.x] : 0.f;
  if (wid == 0) {
    #pragma unroll
    for (int o = 16; o; o >>= 1) v += __shfl_down_sync(0xffffffffu, v, o);
  }
  return v;
}

__global__ void k_zero() { if (threadIdx.x < 3) g_acc[threadIdx.x] = 0.f; }

// split conv weights: W[oc][ic][3][3] fp32 -> g_whi/g_wlo [oc][tap*1024+ic]
__global__ void k_split_w(const float* __restrict__ Wc) {
  int i = blockIdx.x * 256 + threadIdx.x;
  if (i >= 512 * KK) return;
  int oc = i / KK, k = i - oc * KK;
  int tap = k >> 10, ic = k & 1023;
  float v = Wc[(size_t)oc * KK + ic * 9 + tap];
  __nv_bfloat16 hi = __float2bfloat16(v);
  __nv_bfloat16 lo = __float2bfloat16(v - __bfloat162float(hi));
  g_whi[i] = hi; g_wlo[i] = lo;
}

// NCHW fp32 -> NHWC bf16 hi/lo
__global__ void k_nhwc(const float* __restrict__ x) {
  __shared__ float t[32][33];
  int s0 = blockIdx.x * 32, ic0 = blockIdx.y * 32, b = blockIdx.z;
  int tx = threadIdx.x, ty = threadIdx.y;
  #pragma unroll
  for (int i = 0; i < 4; i++)
    t[ty + i * 8][tx] = x[((size_t)b * 1024 + ic0 + ty + i * 8) * HW + s0 + tx];
  __syncthreads();
  #pragma unroll
  for (int i = 0; i < 4; i++) {
    float v = t[tx][ty + i * 8];
    __nv_bfloat16 hi = __float2bfloat16(v);
    __nv_bfloat16 lo = __float2bfloat16(v - __bfloat162float(hi));
    size_t o = ((size_t)b * HW + s0 + ty + i * 8) * 1024 + ic0 + tx;
    g_xhi[o] = hi; g_xlo[o] = lo;
  }
}

// ---------------- HMMA implicit-GEMM conv: 128x128 tile, 3-pass bf16 ----------------
__global__ void __launch_bounds__(256, 1) k_hmma(const float* __restrict__ bias) {
  extern __shared__ __align__(1024) char smc[];
  const uint32_t smb = smem_u32(smc);
  const int tid  = threadIdx.x;
  const int lane = tid & 31, wid = tid >> 5;
  const int m0 = blockIdx.x * 128;
  const int n0 = blockIdx.y * 128;
  const int b  = m0 / HW;
  const int s0 = m0 - b * HW;
  const int wm = wid & 1, wn = wid >> 1;   // warp tile: 64(m) x 32(n)

  float acc[4][4][4];
  #pragma unroll
  for (int i = 0; i < 4; i++)
    #pragma unroll
    for (int j = 0; j < 4; j++)
      #pragma unroll
      for (int k = 0; k < 4; k++) acc[i][j][k] = 0.f;

  // loader decomposition: thread handles chunk col cA of 4 rows (A) + 4 rows (B)
  const int rBase = tid >> 3;           // 0..31
  const int cA    = tid & 7;            // 16B chunk within 128B row
  const int hlA   = cA >> 2;            // 0=hi, 1=lo
  const int k8A   = cA & 3;             // 16B k-subchunk
  const __nv_bfloat16* xsrc = hlA ? g_xlo : g_xhi;
  const __nv_bfloat16* wsrc = hlA ? g_wlo : g_whi;

  // per-row h/w precomputed
  int hh[4], ww4[4];
  #pragma unroll
  for (int t = 0; t < 4; t++) {
    int sp = s0 + rBase + 32 * t;
    hh[t] = sp / 48; ww4[t] = sp - hh[t] * 48;
  }

  #pragma unroll 1
  for (int it = 0; it < NCH + 3; ++it) {
    if (it < NCH) {
      const int st  = it & 3;
      const uint32_t stb = smb + st * STGB;
      const int tap = it >> 5;
      const int ic0 = (it & 31) << 5;
      const int dh = tap / 3 - 1, dw = tap % 3 - 1;
      #pragma unroll
      for (int t = 0; t < 4; t++) {
        int row = rBase + 32 * t;
        int gh = hh[t] + dh, gw = ww4[t] + dw;
        bool ok = ((unsigned)gh < 64u) & ((unsigned)gw < 48u);
        int spg = ok ? (gh * 48 + gw) : 0;
        const void* src = xsrc + (((size_t)b * HW + spg) << 10) + ic0 + k8A * 8;
        cpa16(stb + row * 128 + ((cA ^ (row & 7)) << 4), src, ok ? 16 : 0);
      }
      #pragma unroll
      for (int t = 0; t < 4; t++) {
        int row = rBase + 32 * t;
        const void* src = wsrc + (size_t)(n0 + row) * KK + (it << 5) + k8A * 8;
        cpa16(stb + 16384 + row * 128 + ((cA ^ (row & 7)) << 4), src, 16);
      }
      CPA_COMMIT;
    } else {
      CPA_COMMIT;  // empty group keeps wait_group accounting aligned
    }
    if (it >= 3) {
      CPA_WAIT3;
      __syncthreads();
      const int st = (it - 3) & 3;
      const uint32_t aB = smb + st * STGB;
      const uint32_t bB = aB + 16384;
      #pragma unroll
      for (int s = 0; s < 2; s++) {
        uint32_t ah[4][4], al[4][4], bh[4][2], bl[4][2];
        {
          int rowA = wm * 64 + (lane & 15);
          int khalf = lane >> 4;
          #pragma unroll
          for (int mt = 0; mt < 4; mt++) {
            int r = rowA + mt * 16;
            int cH = 2 * s + khalf;          // hi chunks 0..3
            int cL = 4 + 2 * s + khalf;      // lo chunks 4..7
            ldsm4(ah[mt], aB + r * 128 + ((cH ^ (r & 7)) << 4));
            ldsm4(al[mt], aB + r * 128 + ((cL ^ (r & 7)) << 4));
          }
          int rowB = wn * 32 + (lane & 7);
          int kh = (lane >> 3) & 1;
          #pragma unroll
          for (int nt = 0; nt < 4; nt++) {
            int r = rowB + nt * 8;
            int cH = 2 * s + kh;
            int cL = 4 + 2 * s + kh;
            ldsm2(bh[nt], bB + r * 128 + ((cH ^ (r & 7)) << 4));
            ldsm2(bl[nt], bB + r * 128 + ((cL ^ (r & 7)) << 4));
          }
        }
        #pragma unroll
        for (int mt = 0; mt < 4; mt++)
          #pragma unroll
          for (int nt = 0; nt < 4; nt++) {
            mma16816(acc[mt][nt], ah[mt], bh[nt]);
            mma16816(acc[mt][nt], al[mt], bh[nt]);
            mma16816(acc[mt][nt], ah[mt], bl[nt]);
          }
      }
      __syncthreads();
    }
  }

  // -------- epilogue: smem transpose -> coalesced stores, bias+relu --------
  float* so = (float*)smc;   // [128 oc][128 m] = 64KB
  const int g = lane >> 2, tg = lane & 3;
  #pragma unroll
  for (int mt = 0; mt < 4; mt++)
    #pragma unroll
    for (int nt = 0; nt < 4; nt++) {
      int r0 = wm * 64 + mt * 16 + g;
      int c0 = wn * 32 + nt * 8 + tg * 2;
      so[c0 * 128 + r0]           = acc[mt][nt][0];
      so[(c0 + 1) * 128 + r0]     = acc[mt][nt][1];
      so[c0 * 128 + r0 + 8]       = acc[mt][nt][2];
      so[(c0 + 1) * 128 + r0 + 8] = acc[mt][nt][3];
    }
  __syncthreads();
  #pragma unroll 1
  for (int i = tid; i < 128 * 32; i += 256) {
    int oc = i >> 5, mq = i & 31;
    float4 v = ((const float4*)(so + oc * 128))[mq];
    float bz = bias[n0 + oc];
    v.x = fmaxf(v.x + bz, 0.f); v.y = fmaxf(v.y + bz, 0.f);
    v.z = fmaxf(v.z + bz, 0.f); v.w = fmaxf(v.w + bz, 0.f);
    *(float4*)(g_conv1 + ((size_t)(b * 512 + n0 + oc)) * HW + s0 + mq * 4) = v;
  }
}

// ---------------- heads / losses ----------------
__global__ void k_transpose_h(const float* __restrict__ Wcls, const float* __restrict__ Wbb) {
  int i = blockIdx.x * 256 + threadIdx.x;
  if (i >= 512 * 56) return;
  int ic = i / 56, ch = i - ic * 56;
  float v = 0.f;
  if (ch < 18) v = Wcls[ch * 512 + ic];
  else if (ch < 54) v = Wbb[(ch - 18) * 512 + ic];
  g_wh[i] = v;
}

__global__ void __launch_bounds__(256) k_heads(const float* __restrict__ bcls,
                                               const float* __restrict__ bbb,
                                               float* __restrict__ out) {
  __shared__ __align__(16) float sx[64 * 128];
  __shared__ __align__(16) float sw[64 * 56];
  const int t = blockIdx.x;
  const int b = t / 24;
  const int sp0 = (t % 24) * 128;
  const int tid = threadIdx.x;
  const int sp = tid & 127;
  const int half = tid >> 7;

  float accv[28];
  #pragma unroll
  for (int j = 0; j < 28; j++) accv[j] = 0.f;

  #pragma unroll 1
  for (int ic0 = 0; ic0 < 512; ic0 += 64) {
    __syncthreads();
    {
      float4* dst = (float4*)sx;
      #pragma unroll 1
      for (int i = tid; i < 2048; i += 256) {
        int ic = i >> 5, c = i & 31;
        dst[i] = *(const float4*)(g_conv1 + (size_t)(b * 512 + ic0 + ic) * HW + sp0 + c * 4);
      }
      float4* dw = (float4*)sw;
      const float4* srw = (const float4*)(g_wh + ic0 * 56);
      #pragma unroll 1
      for (int i = tid; i < 896; i += 256) dw[i] = srw[i];
    }
    __syncthreads();
    #pragma unroll 1
    for (int ic = 0; ic < 64; ic++) {
      float xv = sx[ic * 128 + sp];
      const float* wr = sw + ic * 56 + half * 28;
      #pragma unroll
      for (int j = 0; j < 28; j++) accv[j] = fmaf(xv, wr[j], accv[j]);
    }
  }
  const int chb = half * 28;
  #pragma unroll
  for (int j = 0; j < 28; j++) {
    int ch = chb + j;
    if (ch < 54) {
      float bz = (ch < 18) ? bcls[ch] : bbb[ch - 18];
      float v = accv[j] + bz;
      if (ch < 18) g_cls[(size_t)(b * 18 + ch) * HW + sp0 + sp] = v;
      else         out[SZ_PROB + (size_t)(b * 36 + (ch - 18)) * HW + sp0 + sp] = v;
    }
  }
}

__global__ void __launch_bounds__(256) k_cls(const int* __restrict__ label,
                                             float* __restrict__ out) {
  int idx = blockIdx.x * 256 + threadIdx.x;
  float nll = 0.f, cnt = 0.f;
  if (idx < BB * 9 * HW) {
    int b = idx / (9 * HW);
    int rem = idx - b * (9 * HW);
    int a = rem / HW;
    int s = rem - a * HW;
    float l0 = g_cls[(size_t)(b * 18 + a) * HW + s];
    float l1 = g_cls[(size_t)(b * 18 + a + 9) * HW + s];
    float mx = fmaxf(l0, l1);
    float e0 = expf(l0 - mx), e1 = expf(l1 - mx);
    float sum = e0 + e1, inv = 1.f / sum;
    out[(size_t)(b * 18 + a) * HW + s] = e0 * inv;
    out[(size_t)(b * 18 + a + 9) * HW + s] = e1 * inv;
    int lb = label[idx];
    if (lb >= 0) {
      float chosen = lb ? l1 : l0;
      nll = -(chosen - mx - logf(sum));
      cnt = 1.f;
    }
  }
  float s1 = blockReduceSum(nll);
  if (threadIdx.x == 0) atomicAdd(&g_acc[0], s1);
  float s2 = blockReduceSum(cnt);
  if (threadIdx.x == 0) atomicAdd(&g_acc[1], s2);
}

__global__ void __launch_bounds__(256) k_box(const float* __restrict__ tgt,
                                             const float* __restrict__ iw,
                                             const float* __restrict__ ow,
                                             const float* __restrict__ bbox) {
  int i = blockIdx.x * 256 + threadIdx.x;
  float v = 0.f;
  if (i < SZ_BBOX) {
    float d = iw[i] * (bbox[i] - tgt[i]);
    float ad = fabsf(d);
    float l = (ad < (1.f / 9.f)) ? d * d * 4.5f : (ad - (1.f / 18.f));
    v = ow[i] * l;
  }
  float s = blockReduceSum(v);
  if (threadIdx.x == 0) atomicAdd(&g_acc[2], s);
}

__global__ void k_fin(float* out) {
  out[OUT_LCLS] = g_acc[0] / fmaxf(g_acc[1], 1.f);
  out[OUT_LBOX] = g_acc[2] * 0.125f;
}

// ---------------- host ----------------
extern "C" void kernel_launch(void* const* d_in, const int* in_sizes, int n_in,
                              void* d_out, int out_size) {
  const float* base_feat = (const float*)d_in[0];
  const float* W_conv = (const float*)d_in[1];
  const float* b_conv = (const float*)d_in[2];
  const float* W_cls  = (const float*)d_in[3];
  const float* b_cls  = (const float*)d_in[4];
  const float* W_bbox = (const float*)d_in[5];
  const float* b_bbox = (const float*)d_in[6];
  const int* rpn_label = (const int*)d_in[7];
  const float* tgt = (const float*)d_in[8];
  const float* iw  = (const float*)d_in[9];
  const float* ow  = (const float*)d_in[10];
  float* out = (float*)d_out;

  static int init = 0;
  if (!init) {
    cudaFuncSetAttribute(k_hmma, cudaFuncAttributeMaxDynamicSharedMemorySize, SMEM_HMMA);
    init = 1;
  }

  k_zero<<<1, 32>>>();
  k_split_w<<<(512 * KK + 255) / 256, 256>>>(W_conv);
  k_transpose_h<<<(512 * 56 + 255) / 256, 256>>>(W_cls, W_bbox);
  k_nhwc<<<dim3(96, 32, 8), dim3(32, 8)>>>(base_feat);
  k_hmma<<<dim3(192, 4), 256, SMEM_HMMA>>>(b_conv);
  k_heads<<<192, 256>>>(b_cls, b_bbox, out);
  k_cls<<<(BB * 9 * HW + 255) / 256, 256>>>(rpn_label, out);
  k_box<<<(SZ_BBOX + 255) / 256, 256>>>(tgt, iw, ow, out + SZ_PROB);
  k_fin<<<1, 1>>>(out);
}

// round 5
// speedup vs baseline: 2.4991x; 1.1640x over previous
#include <cuda_runtime.h>
#include <cuda_bf16.h>
#include <cstdint>

#define BB 8
#define HW 3072
#define KK 9216
#define SZ_PROB (8*18*3072)
#define SZ_BBOX (8*36*3072)
#define OUT_LCLS (SZ_PROB+SZ_BBOX)
#define OUT_LBOX (SZ_PROB+SZ_BBOX+1)
#define NCH 144
#define STGB 65536
#define SMEM_HMMA (3*STGB)

// ---------------- device scratch ----------------
__device__ float g_conv1[(size_t)BB*512*HW];
__device__ __align__(256) __nv_bfloat16 g_xhi[(size_t)BB*HW*1024];
__device__ __align__(256) __nv_bfloat16 g_xlo[(size_t)BB*HW*1024];
__device__ __align__(256) __nv_bfloat16 g_whi[(size_t)512*KK];
__device__ __align__(256) __nv_bfloat16 g_wlo[(size_t)512*KK];
__device__ float g_wh[512*56];
__device__ float g_cls[SZ_PROB];
__device__ float g_acc[3];

// ---------------- PTX helpers ----------------
__device__ __forceinline__ uint32_t smem_u32(const void* p) {
  uint32_t a;
  asm("{ .reg .u64 t; cvta.to.shared.u64 t, %1; cvt.u32.u64 %0, t; }" : "=r"(a) : "l"(p));
  return a;
}
__device__ __forceinline__ void cpa16(uint32_t dst, const void* src, int sz) {
  asm volatile("cp.async.cg.shared.global [%0], [%1], 16, %2;"
               :: "r"(dst), "l"(src), "r"(sz) : "memory");
}
#define CPA_COMMIT asm volatile("cp.async.commit_group;" ::: "memory")
#define CPA_WAIT1  asm volatile("cp.async.wait_group 1;" ::: "memory")
__device__ __forceinline__ void ldsm4(uint32_t* r, uint32_t a) {
  asm volatile("ldmatrix.sync.aligned.m8n8.x4.shared.b16 {%0,%1,%2,%3}, [%4];"
    : "=r"(r[0]), "=r"(r[1]), "=r"(r[2]), "=r"(r[3]) : "r"(a));
}
__device__ __forceinline__ void ldsm2(uint32_t* r, uint32_t a) {
  asm volatile("ldmatrix.sync.aligned.m8n8.x2.shared.b16 {%0,%1}, [%2];"
    : "=r"(r[0]), "=r"(r[1]) : "r"(a));
}
__device__ __forceinline__ void mma16816(float* c, const uint32_t* a, const uint32_t* b) {
  asm volatile("mma.sync.aligned.m16n8k16.row.col.f32.bf16.bf16.f32 "
    "{%0,%1,%2,%3}, {%4,%5,%6,%7}, {%8,%9}, {%0,%1,%2,%3};"
    : "+f"(c[0]), "+f"(c[1]), "+f"(c[2]), "+f"(c[3])
    : "r"(a[0]), "r"(a[1]), "r"(a[2]), "r"(a[3]), "r"(b[0]), "r"(b[1]));
}

// ---------------- misc ----------------
__device__ __forceinline__ float blockReduceSum(float v) {
  __shared__ float sh[32];
  __syncthreads();
  #pragma unroll
  for (int o = 16; o; o >>= 1) v += __shfl_down_sync(0xffffffffu, v, o);
  int lane = threadIdx.x & 31, wid = threadIdx.x >> 5;
  if (lane == 0) sh[wid] = v;
  __syncthreads();
  int nw = blockDim.x >> 5;
  v = (threadIdx.x < (unsigned)nw) ? sh[threadIdx.x] : 0.f;
  if (wid == 0) {
    #pragma unroll
    for (int o = 16; o; o >>= 1) v += __shfl_down_sync(0xffffffffu, v, o);
  }
  return v;
}

// zero accumulators + head-weight transpose (fused so k_hmma is the 4th launch)
__global__ void k_prep0(const float* __restrict__ Wcls, const float* __restrict__ Wbb) {
  int i = blockIdx.x * 256 + threadIdx.x;
  if (i < 3) g_acc[i] = 0.f;
  if (i < 512 * 56) {
    int ic = i / 56, ch = i - ic * 56;
    float v = 0.f;
    if (ch < 18) v = Wcls[ch * 512 + ic];
    else if (ch < 54) v = Wbb[(ch - 18) * 512 + ic];
    g_wh[i] = v;
  }
}

// split conv weights: W[oc][ic][3][3] fp32 -> g_whi/g_wlo [oc][tap*1024+ic]
__global__ void k_split_w(const float* __restrict__ Wc) {
  int i = blockIdx.x * 256 + threadIdx.x;
  if (i >= 512 * KK) return;
  int oc = i / KK, k = i - oc * KK;
  int tap = k >> 10, ic = k & 1023;
  float v = Wc[(size_t)oc * KK + ic * 9 + tap];
  __nv_bfloat16 hi = __float2bfloat16(v);
  __nv_bfloat16 lo = __float2bfloat16(v - __bfloat162float(hi));
  g_whi[i] = hi; g_wlo[i] = lo;
}

// NCHW fp32 -> NHWC bf16 hi/lo
__global__ void k_nhwc(const float* __restrict__ x) {
  __shared__ float t[32][33];
  int s0 = blockIdx.x * 32, ic0 = blockIdx.y * 32, b = blockIdx.z;
  int tx = threadIdx.x, ty = threadIdx.y;
  #pragma unroll
  for (int i = 0; i < 4; i++)
    t[ty + i * 8][tx] = x[((size_t)b * 1024 + ic0 + ty + i * 8) * HW + s0 + tx];
  __syncthreads();
  #pragma unroll
  for (int i = 0; i < 4; i++) {
    float v = t[tx][ty + i * 8];
    __nv_bfloat16 hi = __float2bfloat16(v);
    __nv_bfloat16 lo = __float2bfloat16(v - __bfloat162float(hi));
    size_t o = ((size_t)b * HW + s0 + ty + i * 8) * 1024 + ic0 + tx;
    g_xhi[o] = hi; g_xlo[o] = lo;
  }
}

// ---------------- HMMA implicit-GEMM conv: 128x128 tile, K-chunk 64, 3-stage, 1 sync/chunk ----------------
__global__ void __launch_bounds__(256, 1) k_hmma(const float* __restrict__ bias) {
  extern __shared__ __align__(1024) char smc[];
  const uint32_t smb = smem_u32(smc);
  const int tid  = threadIdx.x;
  const int lane = tid & 31, wid = tid >> 5;
  const int m0 = blockIdx.x * 128;
  const int n0 = blockIdx.y * 128;
  const int b  = m0 / HW;
  const int s0 = m0 - b * HW;
  const int wm = wid & 1, wn = wid >> 1;   // warp tile: 64(m) x 32(n)

  float acc[4][4][4];
  #pragma unroll
  for (int i = 0; i < 4; i++)
    #pragma unroll
    for (int j = 0; j < 4; j++)
      #pragma unroll
      for (int k = 0; k < 4; k++) acc[i][j][k] = 0.f;

  // loader decomposition: 16 chunk-cols x 16 row-groups, 8 rows each (A and B)
  const int cA  = tid & 15;             // 16B chunk within 256B row
  const int hl  = cA >> 3;              // 0=hi, 1=lo
  const int k16 = cA & 7;               // 16B k-subchunk (8 bf16)
  const int rT  = tid >> 4;             // row base 0..15
  const __nv_bfloat16* xsrc = hl ? g_xlo : g_xhi;
  const __nv_bfloat16* wsrc = hl ? g_wlo : g_whi;

  int hh[8], ww8[8];
  #pragma unroll
  for (int t = 0; t < 8; t++) {
    int sp = s0 + rT + 16 * t;
    hh[t] = sp / 48; ww8[t] = sp - hh[t] * 48;
  }

  // ---- loader lambda-ish macro body via function scope ----
  auto issue_chunk = [&](int c) {
    const int st = c % 3;
    const uint32_t stb = smb + st * STGB;
    const int tap = c >> 4;
    const int icb = (c & 15) << 6;
    const int dh = tap / 3 - 1, dw = tap % 3 - 1;
    const int koff = icb + k16 * 8;
    #pragma unroll
    for (int t = 0; t < 8; t++) {
      int row = rT + 16 * t;
      int gh = hh[t] + dh, gw = ww8[t] + dw;
      bool ok = ((unsigned)gh < 64u) & ((unsigned)gw < 48u);
      int spg = ok ? (gh * 48 + gw) : 0;
      const void* src = xsrc + (((size_t)b * HW + spg) << 10) + koff;
      cpa16(stb + row * 256 + ((cA ^ (row & 7)) << 4), src, ok ? 16 : 0);
    }
    #pragma unroll
    for (int t = 0; t < 8; t++) {
      int row = rT + 16 * t;
      const void* src = wsrc + (size_t)(n0 + row) * KK + (c << 6) + k16 * 8;
      cpa16(stb + 32768 + row * 256 + ((cA ^ (row & 7)) << 4), src, 16);
    }
    CPA_COMMIT;
  };

  // prologue: chunks 0,1
  issue_chunk(0);
  issue_chunk(1);

  #pragma unroll 1
  for (int c = 0; c < NCH; ++c) {
    CPA_WAIT1;
    __syncthreads();
    if (c + 2 < NCH) issue_chunk(c + 2);
    else CPA_COMMIT;

    const uint32_t aB = smb + (c % 3) * STGB;
    const uint32_t bB = aB + 32768;
    #pragma unroll
    for (int s = 0; s < 4; s++) {
      uint32_t ah[4][4], al[4][4], bh[4][2], bl[4][2];
      {
        int rowA = wm * 64 + (lane & 15);
        int khalf = lane >> 4;
        #pragma unroll
        for (int mt = 0; mt < 4; mt++) {
          int r = rowA + mt * 16;
          int cH = 2 * s + khalf;
          int cL = 8 + cH;
          ldsm4(ah[mt], aB + r * 256 + ((cH ^ (r & 7)) << 4));
          ldsm4(al[mt], aB + r * 256 + ((cL ^ (r & 7)) << 4));
        }
        int rowB = wn * 32 + (lane & 7);
        int kh = (lane >> 3) & 1;
        #pragma unroll
        for (int nt = 0; nt < 4; nt++) {
          int r = rowB + nt * 8;
          int cH = 2 * s + kh;
          int cL = 8 + cH;
          ldsm2(bh[nt], bB + r * 256 + ((cH ^ (r & 7)) << 4));
          ldsm2(bl[nt], bB + r * 256 + ((cL ^ (r & 7)) << 4));
        }
      }
      #pragma unroll
      for (int mt = 0; mt < 4; mt++)
        #pragma unroll
        for (int nt = 0; nt < 4; nt++) {
          mma16816(acc[mt][nt], ah[mt], bh[nt]);
          mma16816(acc[mt][nt], al[mt], bh[nt]);
          mma16816(acc[mt][nt], ah[mt], bl[nt]);
        }
    }
  }
  __syncthreads();

  // -------- epilogue: smem transpose -> coalesced stores, bias+relu --------
  float* so = (float*)smc;   // [128 oc][128 m] = 64KB
  const int g = lane >> 2, tg = lane & 3;
  #pragma unroll
  for (int mt = 0; mt < 4; mt++)
    #pragma unroll
    for (int nt = 0; nt < 4; nt++) {
      int r0 = wm * 64 + mt * 16 + g;
      int c0 = wn * 32 + nt * 8 + tg * 2;
      so[c0 * 128 + r0]           = acc[mt][nt][0];
      so[(c0 + 1) * 128 + r0]     = acc[mt][nt][1];
      so[c0 * 128 + r0 + 8]       = acc[mt][nt][2];
      so[(c0 + 1) * 128 + r0 + 8] = acc[mt][nt][3];
    }
  __syncthreads();
  #pragma unroll 1
  for (int i = tid; i < 128 * 32; i += 256) {
    int oc = i >> 5, mq = i & 31;
    float4 v = ((const float4*)(so + oc * 128))[mq];
    float bz = bias[n0 + oc];
    v.x = fmaxf(v.x + bz, 0.f); v.y = fmaxf(v.y + bz, 0.f);
    v.z = fmaxf(v.z + bz, 0.f); v.w = fmaxf(v.w + bz, 0.f);
    *(float4*)(g_conv1 + ((size_t)(b * 512 + n0 + oc)) * HW + s0 + mq * 4) = v;
  }
}

// ---------------- heads / losses ----------------
__global__ void __launch_bounds__(256) k_heads(const float* __restrict__ bcls,
                                               const float* __restrict__ bbb,
                                               float* __restrict__ out) {
  __shared__ __align__(16) float sx[64 * 128];
  __shared__ __align__(16) float sw[64 * 56];
  const int t = blockIdx.x;
  const int b = t / 24;
  const int sp0 = (t % 24) * 128;
  const int tid = threadIdx.x;
  const int sp = tid & 127;
  const int half = tid >> 7;

  float accv[28];
  #pragma unroll
  for (int j = 0; j < 28; j++) accv[j] = 0.f;

  #pragma unroll 1
  for (int ic0 = 0; ic0 < 512; ic0 += 64) {
    __syncthreads();
    {
      float4* dst = (float4*)sx;
      #pragma unroll 1
      for (int i = tid; i < 2048; i += 256) {
        int ic = i >> 5, c = i & 31;
        dst[i] = *(const float4*)(g_conv1 + (size_t)(b * 512 + ic0 + ic) * HW + sp0 + c * 4);
      }
      float4* dw = (float4*)sw;
      const float4* srw = (const float4*)(g_wh + ic0 * 56);
      #pragma unroll 1
      for (int i = tid; i < 896; i += 256) dw[i] = srw[i];
    }
    __syncthreads();
    #pragma unroll 1
    for (int ic = 0; ic < 64; ic++) {
      float xv = sx[ic * 128 + sp];
      const float* wr = sw + ic * 56 + half * 28;
      #pragma unroll
      for (int j = 0; j < 28; j++) accv[j] = fmaf(xv, wr[j], accv[j]);
    }
  }
  const int chb = half * 28;
  #pragma unroll
  for (int j = 0; j < 28; j++) {
    int ch = chb + j;
    if (ch < 54) {
      float bz = (ch < 18) ? bcls[ch] : bbb[ch - 18];
      float v = accv[j] + bz;
      if (ch < 18) g_cls[(size_t)(b * 18 + ch) * HW + sp0 + sp] = v;
      else         out[SZ_PROB + (size_t)(b * 36 + (ch - 18)) * HW + sp0 + sp] = v;
    }
  }
}

__global__ void __launch_bounds__(256) k_cls(const int* __restrict__ label,
                                             float* __restrict__ out) {
  int idx = blockIdx.x * 256 + threadIdx.x;
  float nll = 0.f, cnt = 0.f;
  if (idx < BB * 9 * HW) {
    int b = idx / (9 * HW);
    int rem = idx - b * (9 * HW);
    int a = rem / HW;
    int s = rem - a * HW;
    float l0 = g_cls[(size_t)(b * 18 + a) * HW + s];
    float l1 = g_cls[(size_t)(b * 18 + a + 9) * HW + s];
    float mx = fmaxf(l0, l1);
    float e0 = expf(l0 - mx), e1 = expf(l1 - mx);
    float sum = e0 + e1, inv = 1.f / sum;
    out[(size_t)(b * 18 + a) * HW + s] = e0 * inv;
    out[(size_t)(b * 18 + a + 9) * HW + s] = e1 * inv;
    int lb = label[idx];
    if (lb >= 0) {
      float chosen = lb ? l1 : l0;
      nll = -(chosen - mx - logf(sum));
      cnt = 1.f;
    }
  }
  float s1 = blockReduceSum(nll);
  if (threadIdx.x == 0) atomicAdd(&g_acc[0], s1);
  float s2 = blockReduceSum(cnt);
  if (threadIdx.x == 0) atomicAdd(&g_acc[1], s2);
}

__global__ void __launch_bounds__(256) k_box(const float* __restrict__ tgt,
                                             const float* __restrict__ iw,
                                             const float* __restrict__ ow,
                                             const float* __restrict__ bbox) {
  int i = blockIdx.x * 256 + threadIdx.x;
  float v = 0.f;
  if (i < SZ_BBOX) {
    float d = iw[i] * (bbox[i] - tgt[i]);
    float ad = fabsf(d);
    float l = (ad < (1.f / 9.f)) ? d * d * 4.5f : (ad - (1.f / 18.f));
    v = ow[i] * l;
  }
  float s = blockReduceSum(v);
  if (threadIdx.x == 0) atomicAdd(&g_acc[2], s);
}

__global__ void k_fin(float* out) {
  out[OUT_LCLS] = g_acc[0] / fmaxf(g_acc[1], 1.f);
  out[OUT_LBOX] = g_acc[2] * 0.125f;
}

// ---------------- host ----------------
extern "C" void kernel_launch(void* const* d_in, const int* in_sizes, int n_in,
                              void* d_out, int out_size) {
  const float* base_feat = (const float*)d_in[0];
  const float* W_conv = (const float*)d_in[1];
  const float* b_conv = (const float*)d_in[2];
  const float* W_cls  = (const float*)d_in[3];
  const float* b_cls  = (const float*)d_in[4];
  const float* W_bbox = (const float*)d_in[5];
  const float* b_bbox = (const float*)d_in[6];
  const int* rpn_label = (const int*)d_in[7];
  const float* tgt = (const float*)d_in[8];
  const float* iw  = (const float*)d_in[9];
  const float* ow  = (const float*)d_in[10];
  float* out = (float*)d_out;

  static int init = 0;
  if (!init) {
    cudaFuncSetAttribute(k_hmma, cudaFuncAttributeMaxDynamicSharedMemorySize, SMEM_HMMA);
    init = 1;
  }

  k_prep0<<<(512 * 56 + 255) / 256, 256>>>(W_cls, W_bbox);
  k_split_w<<<(512 * KK + 255) / 256, 256>>>(W_conv);
  k_nhwc<<<dim3(96, 32, 8), dim3(32, 8)>>>(base_feat);
  k_hmma<<<dim3(192, 4), 256, SMEM_HMMA>>>(b_conv);
  k_heads<<<192, 256>>>(b_cls, b_bbox, out);
  k_cls<<<(BB * 9 * HW + 255) / 256, 256>>>(rpn_label, out);
  k_box<<<(SZ_BBOX + 255) / 256, 256>>>(tgt, iw, ow, out + SZ_PROB);
  k_fin<<<1, 1>>>(out);
}